// round 9
// baseline (speedup 1.0000x reference)
#include <cuda_runtime.h>
#include <cuda_fp16.h>
#include <math.h>
#include <stdint.h>

#define BB 8
#define TT 4096
#define DD 768
#define HH 12
#define MM (BB*TT)          // 32768

// Scratch (device globals: allocation-free rule)
__device__ float  g_Q[(size_t)MM*DD];
__device__ float  g_K[(size_t)MM*DD];
__device__ float  g_V[(size_t)MM*DD];
__device__ float  g_y[(size_t)MM*DD];
__device__ __half g_xh[(size_t)MM*DD];         // x in fp16
__device__ __half g_attnh[(size_t)MM*DD];      // attention output in fp16
__device__ __half g_Wth[(size_t)3072*DD];      // transposed weights fp16: rows 0-2303 QKV, 2304-3071 O
__device__ float  g_bqkv[3*DD];                // packed QKV bias

// ===========================================================================
// fp32 -> fp16 conversion: 8 elements per thread
// ===========================================================================
__global__ void __launch_bounds__(256)
f2h_kernel(const float* __restrict__ src)
{
    size_t i = ((size_t)blockIdx.x * 256 + threadIdx.x) * 8;
    float4 a = *(const float4*)(src + i);
    float4 b = *(const float4*)(src + i + 4);
    __half2 h[4];
    h[0] = __floats2half2_rn(a.x, a.y);
    h[1] = __floats2half2_rn(a.z, a.w);
    h[2] = __floats2half2_rn(b.x, b.y);
    h[3] = __floats2half2_rn(b.z, b.w);
    *(uint2*)(g_xh + i)     = *(uint2*)&h[0];
    *(uint2*)(g_xh + i + 4) = *(uint2*)&h[2];
}

// ===========================================================================
// Pack QKV bias into one array
// ===========================================================================
__global__ void __launch_bounds__(256)
pack_bias(const float* __restrict__ bq, const float* __restrict__ bk,
          const float* __restrict__ bv)
{
    for (int i = threadIdx.x; i < 3 * DD; i += 256) {
        const float* s = (i < DD) ? bq : (i < 2 * DD) ? bk : bv;
        g_bqkv[i] = s[i % DD];
    }
}

// ===========================================================================
// Weight transpose + fp16: g_Wth[z*768 + n][k] = (half)Wz[k][n]
// ===========================================================================
__global__ void __launch_bounds__(256)
transpose_w(const float* __restrict__ W0, const float* __restrict__ W1,
            const float* __restrict__ W2, const float* __restrict__ W3)
{
    __shared__ float t[32][33];
    const float* W = (blockIdx.z == 0) ? W0 : (blockIdx.z == 1) ? W1
                   : (blockIdx.z == 2) ? W2 : W3;
    __half* Wt = g_Wth + (size_t)blockIdx.z * DD * DD;
    int x  = blockIdx.x * 32 + threadIdx.x;
    int y0 = blockIdx.y * 32 + threadIdx.y;
#pragma unroll
    for (int i = 0; i < 4; i++)
        t[threadIdx.y + 8 * i][threadIdx.x] = W[(size_t)(y0 + 8 * i) * DD + x];
    __syncthreads();
    int x2 = blockIdx.y * 32 + threadIdx.x;
    int y2 = blockIdx.x * 32 + threadIdx.y;
#pragma unroll
    for (int i = 0; i < 4; i++)
        Wt[(size_t)(y2 + 8 * i) * DD + x2] = __float2half(t[threadIdx.x][threadIdx.y + 8 * i]);
}

// ===========================================================================
// FP16 tensor-core GEMM, CTA tile 128x256, 8 warps of 64x64, 4-stage ring.
// A [m][k] fp16 (g_xh or g_attnh), B = g_Wth rows [nw0 + n][k]. mma.m16n8k16.
// mode 0: fused QKV (N=2304 grid, out split to g_Q/g_K/g_V, bias g_bqkv)
// mode 1: O proj   (N=768 grid, out g_y, bias bo, residual res)
// ===========================================================================
#define KH 64                  // halves per k-tile (128B rows)
#define NKT (DD/KH)            // 12
#define A_STG 16384            // 128 x 128B
#define B_STG 32768            // 256 x 128B
#define STAGE (A_STG + B_STG)  // 49152
#define NSTG 4
#define GSMEM (NSTG * STAGE)   // 196608

__device__ __forceinline__ void ldsm_x4(uint32_t* r, uint32_t addr) {
    asm volatile("ldmatrix.sync.aligned.m8n8.x4.shared.b16 {%0,%1,%2,%3}, [%4];"
                 : "=r"(r[0]), "=r"(r[1]), "=r"(r[2]), "=r"(r[3]) : "r"(addr));
}
__device__ __forceinline__ void mma_f16(float c[4], const uint32_t a[4], const uint32_t b[2]) {
    asm volatile(
        "mma.sync.aligned.m16n8k16.row.col.f32.f16.f16.f32 "
        "{%0,%1,%2,%3},{%4,%5,%6,%7},{%8,%9},{%0,%1,%2,%3};"
        : "+f"(c[0]), "+f"(c[1]), "+f"(c[2]), "+f"(c[3])
        : "r"(a[0]), "r"(a[1]), "r"(a[2]), "r"(a[3]), "r"(b[0]), "r"(b[1]));
}

__global__ void __launch_bounds__(256, 1)
gemm_h(int asel, int nw0, int mode,
       const float* __restrict__ bias_o, const float* __restrict__ res)
{
    extern __shared__ char smem[];
    const uint32_t sbase = (uint32_t)__cvta_generic_to_shared(smem);

    const int tid  = threadIdx.x;
    const int warp = tid >> 5;
    const int lane = tid & 31;
    const int g    = lane >> 2;
    const int tg   = lane & 3;
    const int wm0  = (warp >> 2) * 64;   // 2 warp-rows
    const int wn0  = (warp & 3) * 64;    // 4 warp-cols

    const int m0 = blockIdx.y * 128;
    const int n0 = blockIdx.x * 256;

    const __half* Ap = (asel == 0) ? g_xh : g_attnh;
    const __half* Bt = g_Wth + (size_t)(nw0 + n0) * DD;

    float acc[4][8][4];
#pragma unroll
    for (int i = 0; i < 4; i++)
#pragma unroll
        for (int j = 0; j < 8; j++)
#pragma unroll
            for (int r = 0; r < 4; r++) acc[i][j][r] = 0.f;

    // ---- stage loader: 16B chunks, 128B rows, chunk-XOR swizzle ----
    auto load_stage = [&](int kt) {
        const int slot = kt & 3;
        const int k0 = kt * KH;
        const uint32_t abase = sbase + slot * STAGE;
        const uint32_t bbase = abase + A_STG;
#pragma unroll
        for (int i = 0; i < 4; i++) {               // A: 128 rows x 8 chunks
            int idx = tid + i * 256;
            int r = idx >> 3, c = idx & 7;
            uint32_t sw = (uint32_t)(c ^ (r & 7)) * 16;
            const __half* gp = Ap + (size_t)(m0 + r) * DD + k0 + c * 8;
            asm volatile("cp.async.cg.shared.global [%0], [%1], 16;"
                         :: "r"(abase + (uint32_t)r * 128 + sw), "l"(gp));
        }
#pragma unroll
        for (int i = 0; i < 8; i++) {               // B: 256 n-rows x 8 chunks
            int idx = tid + i * 256;
            int r = idx >> 3, c = idx & 7;
            uint32_t sw = (uint32_t)(c ^ (r & 7)) * 16;
            const __half* gp = Bt + (size_t)r * DD + k0 + c * 8;
            asm volatile("cp.async.cg.shared.global [%0], [%1], 16;"
                         :: "r"(bbase + (uint32_t)r * 128 + sw), "l"(gp));
        }
        asm volatile("cp.async.commit_group;");
    };

    load_stage(0);
    load_stage(1);
    load_stage(2);

    for (int kt = 0; kt < NKT; kt++) {
        const int slot = kt & 3;
        if (kt + 3 < NKT) load_stage(kt + 3);
        int wg = NKT - 1 - kt; if (wg > 3) wg = 3;
        if      (wg == 3) asm volatile("cp.async.wait_group 3;");
        else if (wg == 2) asm volatile("cp.async.wait_group 2;");
        else if (wg == 1) asm volatile("cp.async.wait_group 1;");
        else              asm volatile("cp.async.wait_group 0;");
        __syncthreads();

        const uint32_t abase = sbase + slot * STAGE;
        const uint32_t bbase = abase + A_STG;

#pragma unroll
        for (int ks = 0; ks < 4; ks++) {            // 4 x k16 per k-tile
            uint32_t af[4][4], bf[4][4];
#pragma unroll
            for (int i = 0; i < 4; i++) {           // A: 4 m16 tiles
                int row = wm0 + i * 16 + (lane & 15);
                int chunk = ks * 2 + (lane >> 4);
                uint32_t addr = abase + (uint32_t)row * 128
                              + (uint32_t)((chunk ^ (row & 7)) * 16);
                ldsm_x4(af[i], addr);
            }
#pragma unroll
            for (int jp = 0; jp < 4; jp++) {        // B: 4 x (two n8 tiles)
                int nrow = wn0 + jp * 16 + (lane & 7) + ((lane >> 4) << 3);
                int chunk = ks * 2 + ((lane >> 3) & 1);
                uint32_t addr = bbase + (uint32_t)nrow * 128
                              + (uint32_t)((chunk ^ (nrow & 7)) * 16);
                ldsm_x4(bf[jp], addr);
            }
#pragma unroll
            for (int i = 0; i < 4; i++)
#pragma unroll
                for (int j = 0; j < 8; j++)
                    mma_f16(acc[i][j], af[i], bf[j >> 1] + (j & 1) * 2);
        }
        __syncthreads();
    }

    // ---- epilogue ----
    float* C;
    int coff;          // column offset within C
    if (mode == 0) {
        int qkv = n0 / DD;
        C = (qkv == 0) ? g_Q : (qkv == 1) ? g_K : g_V;
        coff = n0 % DD;
    } else {
        C = g_y;
        coff = n0;
    }
#pragma unroll
    for (int i = 0; i < 4; i++) {
#pragma unroll
        for (int j = 0; j < 8; j++) {
            int row = m0 + wm0 + i * 16 + g;
            int nlocal = wn0 + j * 8 + tg * 2;          // 0..255 in tile
            int col = coff + nlocal;
            size_t i0 = (size_t)row * DD + col;
            size_t i1 = i0 + (size_t)8 * DD;
            float b0v, b1v;
            if (mode == 0) {
                b0v = g_bqkv[n0 + nlocal];
                b1v = g_bqkv[n0 + nlocal + 1];
            } else {
                b0v = bias_o[col];
                b1v = bias_o[col + 1];
            }
            float2 v0 = make_float2(acc[i][j][0] + b0v, acc[i][j][1] + b1v);
            float2 v1 = make_float2(acc[i][j][2] + b0v, acc[i][j][3] + b1v);
            if (mode == 1) {
                float2 r0 = *(const float2*)(res + i0);
                float2 r1 = *(const float2*)(res + i1);
                v0.x += r0.x; v0.y += r0.y;
                v1.x += r1.x; v1.y += r1.y;
            }
            *(float2*)(C + i0) = v0;
            *(float2*)(C + i1) = v1;
        }
    }
}

// ===========================================================================
// Local attention: {t-3, t, t+3}. One warp handles TWO heads (float4/lane,
// 16-lane groups). Q/K/V fp32 in, fp16 out.
// ===========================================================================
__global__ void __launch_bounds__(256)
attn_kernel()
{
    const int warp = threadIdx.x >> 5;
    const int lane = threadIdx.x & 31;
    const int gw = blockIdx.x * 8 + warp;      // 0 .. B*T*6-1
    const int hp = gw % 6;                     // head pair
    const int bt = gw / 6;
    const int t  = bt & (TT - 1);
    const int b  = bt >> 12;

    const int h   = hp * 2 + (lane >> 4);
    const int sub = lane & 15;
    const size_t qoff = (size_t)bt * DD + h * 64 + sub * 4;
    const float4 q = *(const float4*)(g_Q + qoff);

    float w[3];
    size_t kb[3];
#pragma unroll
    for (int o = 0; o < 3; o++) {
        int tt = t + (o - 1) * 3;
        bool valid = (tt >= 0) && (tt < TT);
        int ttc = valid ? tt : t;
        kb[o] = ((size_t)(b * TT + ttc)) * DD + h * 64 + sub * 4;
        float4 k4 = *(const float4*)(g_K + kb[o]);
        float p = q.x * k4.x + q.y * k4.y + q.z * k4.z + q.w * k4.w;
#pragma unroll
        for (int d2 = 8; d2 > 0; d2 >>= 1)     // reduce within 16-lane group
            p += __shfl_xor_sync(0xffffffffu, p, d2);
        w[o] = valid ? p * 0.125f : -INFINITY;  // 1/sqrt(64)
    }
    float m = fmaxf(w[0], fmaxf(w[1], w[2]));
    float s = 0.f;
#pragma unroll
    for (int o = 0; o < 3; o++) { w[o] = __expf(w[o] - m); s += w[o]; }
    float inv = 1.f / s;

    float4 a = make_float4(0.f, 0.f, 0.f, 0.f);
#pragma unroll
    for (int o = 0; o < 3; o++) {
        float4 v4 = *(const float4*)(g_V + kb[o]);
        a.x += w[o] * v4.x; a.y += w[o] * v4.y;
        a.z += w[o] * v4.z; a.w += w[o] * v4.w;
    }
    __half2 h0 = __floats2half2_rn(a.x * inv, a.y * inv);
    __half2 h1 = __floats2half2_rn(a.z * inv, a.w * inv);
    uint2 pk = make_uint2(*(uint32_t*)&h0, *(uint32_t*)&h1);
    *(uint2*)(g_attnh + qoff) = pk;
}

// ===========================================================================
// LayerNorm over last dim (768): 192 threads/row, float4 per thread.
// ===========================================================================
__global__ void __launch_bounds__(192)
ln_kernel(const float* __restrict__ gamma, const float* __restrict__ beta,
          float* __restrict__ out)
{
    const int row = blockIdx.x;
    const int tid = threadIdx.x;
    const int lane = tid & 31;
    const int warp = tid >> 5;

    float4 v = *(const float4*)(g_y + (size_t)row * DD + tid * 4);
    float s  = v.x + v.y + v.z + v.w;
    float sq = v.x * v.x + v.y * v.y + v.z * v.z + v.w * v.w;
#pragma unroll
    for (int d2 = 16; d2 > 0; d2 >>= 1) {
        s  += __shfl_xor_sync(0xffffffffu, s, d2);
        sq += __shfl_xor_sync(0xffffffffu, sq, d2);
    }
    __shared__ float rs[6], rq[6];
    if (lane == 0) { rs[warp] = s; rq[warp] = sq; }
    __syncthreads();
    if (warp == 0) {
        float a  = (lane < 6) ? rs[lane] : 0.f;
        float b2 = (lane < 6) ? rq[lane] : 0.f;
#pragma unroll
        for (int d2 = 4; d2 > 0; d2 >>= 1) {
            a  += __shfl_xor_sync(0xffffffffu, a, d2);
            b2 += __shfl_xor_sync(0xffffffffu, b2, d2);
        }
        if (lane == 0) { rs[0] = a; rq[0] = b2; }
    }
    __syncthreads();
    const float mu   = rs[0] * (1.f / 768.f);
    const float var  = rq[0] * (1.f / 768.f) - mu * mu;
    const float rstd = rsqrtf(var + 1e-5f);

    float4 gm = *(const float4*)(gamma + tid * 4);
    float4 bt = *(const float4*)(beta + tid * 4);
    float4 o;
    o.x = (v.x - mu) * rstd * gm.x + bt.x;
    o.y = (v.y - mu) * rstd * gm.y + bt.y;
    o.z = (v.z - mu) * rstd * gm.z + bt.z;
    o.w = (v.w - mu) * rstd * gm.w + bt.w;
    *(float4*)(out + (size_t)row * DD + tid * 4) = o;
}

// ===========================================================================
extern "C" void kernel_launch(void* const* d_in, const int* in_sizes, int n_in,
                              void* d_out, int out_size)
{
    const float* x     = (const float*)d_in[0];
    const float* Wq    = (const float*)d_in[1];
    const float* bq    = (const float*)d_in[2];
    const float* Wk    = (const float*)d_in[3];
    const float* bk    = (const float*)d_in[4];
    const float* Wv    = (const float*)d_in[5];
    const float* bv    = (const float*)d_in[6];
    const float* Wo    = (const float*)d_in[7];
    const float* bo    = (const float*)d_in[8];
    const float* gamma = (const float*)d_in[9];
    const float* beta  = (const float*)d_in[10];
    float* out = (float*)d_out;

    cudaFuncSetAttribute(gemm_h, cudaFuncAttributeMaxDynamicSharedMemorySize, GSMEM);

    f2h_kernel<<<(MM * DD) / (256 * 8), 256>>>(x);
    pack_bias<<<1, 256>>>(bq, bk, bv);
    transpose_w<<<dim3(DD / 32, DD / 32, 4), dim3(32, 8)>>>(Wq, Wk, Wv, Wo);

    // Fused QKV: N = 2304
    gemm_h<<<dim3(9, MM / 128), 256, GSMEM>>>(0, 0, 0, nullptr, nullptr);

    attn_kernel<<<(MM * 6) / 8, 256>>>();

    // O projection: N = 768, weights at rows 2304.., residual x
    gemm_h<<<dim3(3, MM / 128), 256, GSMEM>>>(1, 3 * DD, 1, bo, x);

    ln_kernel<<<MM, 192>>>(gamma, beta, out);
}